// round 7
// baseline (speedup 1.0000x reference)
#include <cuda_runtime.h>
#include <cuda_fp16.h>
#include <cstdint>
#include <math.h>

#define TPB 256
#define KCH_MAX 16

// scratch partials: [kchunk][n*3+c][128*128] floats = 16*12*16384 = 12.6MB
__device__ float g_scratch[KCH_MAX * 12 * 16384];

static __device__ __forceinline__ uint32_t s2u(const void* p) {
    uint32_t a;
    asm("{ .reg .u64 t; cvta.to.shared.u64 t, %1; cvt.u32.u64 %0, t; }" : "=r"(a) : "l"(p));
    return a;
}
static __device__ __forceinline__ float fast_exp2(float x) {
    float y; asm("ex2.approx.ftz.f32 %0, %1;" : "=f"(y) : "f"(x)); return y;
}
static __device__ __forceinline__ uint32_t pack_h2(float lo, float hi) {
    uint32_t u;
    asm("cvt.rn.f16x2.f32 %0, %1, %2;" : "=r"(u) : "f"(hi), "f"(lo));  // d.lo = %2
    return u;
}
static __device__ __forceinline__ uint32_t sw128(uint32_t off) {
    return off ^ ((off >> 3) & 0x70);
}
static __device__ __forceinline__ void ldsm_x4(uint32_t addr, uint32_t& r0, uint32_t& r1,
                                               uint32_t& r2, uint32_t& r3) {
    asm volatile("ldmatrix.sync.aligned.m8n8.x4.shared.b16 {%0,%1,%2,%3}, [%4];"
                 : "=r"(r0), "=r"(r1), "=r"(r2), "=r"(r3) : "r"(addr));
}
static __device__ __forceinline__ void mma16816(float* c, uint32_t a0, uint32_t a1,
                                                uint32_t a2, uint32_t a3,
                                                uint32_t b0, uint32_t b1) {
    asm volatile(
        "mma.sync.aligned.m16n8k16.row.col.f32.f16.f16.f32 "
        "{%0,%1,%2,%3}, {%4,%5,%6,%7}, {%8,%9}, {%0,%1,%2,%3};"
        : "+f"(c[0]), "+f"(c[1]), "+f"(c[2]), "+f"(c[3])
        : "r"(a0), "r"(a1), "r"(a2), "r"(a3), "r"(b0), "r"(b1));
}

// CTA = (kchunk of 64 points, channel c, batch n).
// partial[128h x 128w] = sum_p ey[h,p] * (ex[w,p] * v[p,c]) -> g_scratch (plain STG)
__global__ void __launch_bounds__(TPB)
splat2d_hmma_kernel(const float* __restrict__ coords,   // [N,P,2]
                    const float* __restrict__ values,   // [N,P,3]
                    const float* __restrict__ sigma,    // [N,1]
                    int P) {
    __shared__ float bx[64], by[64], vc[64];
    __shared__ __align__(1024) char At[128 * 128];   // ey tile: 128h x 64p fp16, SW128
    __shared__ __align__(1024) char Bt[128 * 128];   // (ex*v) : 128w x 64p fp16, SW128

    const int tid  = threadIdx.x;
    const int kp   = blockIdx.x;
    const int c    = blockIdx.y;
    const int n    = blockIdx.z;
    const int p0   = kp * 64;

    const float sg = sigma[n];
    const float a_ = sqrtf(0.72134752044448169f) / sg;   // sqrt(log2(e)/2)/sigma

    const float2* cb2 = (const float2*)coords + (size_t)n * P;
    const float*  vb  = values + (size_t)n * P * 3;

    if (tid < 64) {
        const float2 cd = cb2[p0 + tid];
        bx[tid] = a_ * cd.x;
        by[tid] = a_ * cd.y;
        vc[tid] = vb[(p0 + tid) * 3 + c];
    }
    __syncthreads();

    const uint32_t Abase = s2u(At);
    const uint32_t Bbase = s2u(Bt);

    // ---- A tile: ey[h][p] ----
    for (int task = tid; task < 1024; task += TPB) {
        const int h = task >> 3, pg = task & 7;
        const float ah = a_ * (float)h;
        float e[8];
        #pragma unroll
        for (int i = 0; i < 8; ++i) {
            const float d = ah - by[pg * 8 + i];
            e[i] = fast_exp2(-d * d);
        }
        const uint32_t q0 = pack_h2(e[0], e[1]);
        const uint32_t q1 = pack_h2(e[2], e[3]);
        const uint32_t q2 = pack_h2(e[4], e[5]);
        const uint32_t q3 = pack_h2(e[6], e[7]);
        asm volatile("st.shared.v4.b32 [%0], {%1,%2,%3,%4};"
                     :: "r"(Abase + sw128((uint32_t)(h * 128 + pg * 16))),
                        "r"(q0), "r"(q1), "r"(q2), "r"(q3));
    }
    // ---- B tile: (ex * vc)[w][p] ----
    for (int task = tid; task < 1024; task += TPB) {
        const int w = task >> 3, pg = task & 7;
        const float aw = a_ * (float)w;
        float m[8];
        #pragma unroll
        for (int i = 0; i < 8; ++i) {
            const float d = aw - bx[pg * 8 + i];
            m[i] = fast_exp2(-d * d) * vc[pg * 8 + i];
        }
        const uint32_t q0 = pack_h2(m[0], m[1]);
        const uint32_t q1 = pack_h2(m[2], m[3]);
        const uint32_t q2 = pack_h2(m[4], m[5]);
        const uint32_t q3 = pack_h2(m[6], m[7]);
        asm volatile("st.shared.v4.b32 [%0], {%1,%2,%3,%4};"
                     :: "r"(Bbase + sw128((uint32_t)(w * 128 + pg * 16))),
                        "r"(q0), "r"(q1), "r"(q2), "r"(q3));
    }
    __syncthreads();

    // ---- consumer: 8 warps, warp tile 32h x 64w ----
    const int wid  = tid >> 5;
    const int lane = tid & 31;
    const int h0   = (wid & 3) * 32;
    const int w0   = (wid >> 2) * 64;

    float acc[2][8][4];
    #pragma unroll
    for (int mb = 0; mb < 2; ++mb)
        #pragma unroll
        for (int nb = 0; nb < 8; ++nb)
            #pragma unroll
            for (int j = 0; j < 4; ++j) acc[mb][nb][j] = 0.f;

    const int a_row = lane & 15;
    const int a_kb  = (lane >> 4) << 4;
    const int b_row = (((lane >> 4) & 1) << 3) + (lane & 7);
    const int b_kb  = ((lane >> 3) & 1) << 4;

    #pragma unroll
    for (int ks = 0; ks < 4; ++ks) {
        const uint32_t kbyte = ks * 32;   // 16 f16 per K-step

        uint32_t a[2][4];
        #pragma unroll
        for (int mb = 0; mb < 2; ++mb) {
            const uint32_t row = (uint32_t)(h0 + mb * 16 + a_row);
            ldsm_x4(Abase + sw128(row * 128 + kbyte + a_kb),
                    a[mb][0], a[mb][1], a[mb][2], a[mb][3]);
        }
        uint32_t b[4][4];
        #pragma unroll
        for (int nb16 = 0; nb16 < 4; ++nb16) {
            const uint32_t row = (uint32_t)(w0 + nb16 * 16 + b_row);
            ldsm_x4(Bbase + sw128(row * 128 + kbyte + b_kb),
                    b[nb16][0], b[nb16][1], b[nb16][2], b[nb16][3]);
        }
        #pragma unroll
        for (int mb = 0; mb < 2; ++mb)
            #pragma unroll
            for (int nb = 0; nb < 8; ++nb)
                mma16816(acc[mb][nb],
                         a[mb][0], a[mb][1], a[mb][2], a[mb][3],
                         b[nb >> 1][(nb & 1) ? 2 : 0], b[nb >> 1][(nb & 1) ? 3 : 1]);
    }

    // ---- epilogue: vectorized plain stores of the partial tile ----
    const int r  = lane >> 2;
    const int c2 = (lane & 3) * 2;
    float* sc = g_scratch + (size_t)kp * (12 * 16384) + (((size_t)n * 3 + c) << 14);
    #pragma unroll
    for (int mb = 0; mb < 2; ++mb) {
        #pragma unroll
        for (int nb = 0; nb < 8; ++nb) {
            const int hh = h0 + mb * 16 + r;
            const int ww = w0 + nb * 8 + c2;
            float* p = sc + hh * 128 + ww;
            *reinterpret_cast<float2*>(p) =
                make_float2(acc[mb][nb][0], acc[mb][nb][1]);
            *reinterpret_cast<float2*>(p + 8 * 128) =
                make_float2(acc[mb][nb][2], acc[mb][nb][3]);
        }
    }
}

// out4[g] = sum_k scratch4[k*49152 + g],  g in [0, 49152)
__global__ void __launch_bounds__(TPB)
splat2d_reduce_kernel(float4* __restrict__ out, int kch) {
    const int g = blockIdx.x * TPB + threadIdx.x;
    const float4* s = reinterpret_cast<const float4*>(g_scratch);
    float4 a = s[g];
    #pragma unroll
    for (int k = 1; k < KCH_MAX; ++k) {
        if (k >= kch) break;
        const float4 b = s[(size_t)k * 49152 + g];
        a.x += b.x; a.y += b.y; a.z += b.z; a.w += b.w;
    }
    out[g] = a;
}

extern "C" void kernel_launch(void* const* d_in, const int* in_sizes, int n_in,
                              void* d_out, int out_size) {
    const float* coords = (const float*)d_in[0];   // [N,P,2]
    const float* values = (const float*)d_in[1];   // [N,P,C]
    const float* sigma  = (const float*)d_in[2];   // [N,1]

    const int N = in_sizes[2];
    const int P = in_sizes[0] / (2 * N);           // 1024
    const int kch = P / 64;                        // 16

    dim3 grid(kch, 3, N);                          // 16 x 3 x 4 = 192 CTAs
    splat2d_hmma_kernel<<<grid, TPB>>>(coords, values, sigma, P);

    const int n_f4 = out_size / 4;                 // 49152
    splat2d_reduce_kernel<<<n_f4 / TPB, TPB>>>((float4*)d_out, kch);
}

// round 8
// speedup vs baseline: 1.1373x; 1.1373x over previous
#include <cuda_runtime.h>
#include <cuda_fp16.h>
#include <cstdint>
#include <math.h>

#define TPB 256
#define PCH 128                 // points per main-kernel CTA (2 sub-tiles of 64)
#define KCH_MAX 8

// scratch partials: [kchunk][n*3+c][128*128] floats = 8*12*16384*4B = 6.3MB
__device__ float g_scratch[KCH_MAX * 12 * 16384];

static __device__ __forceinline__ uint32_t s2u(const void* p) {
    uint32_t a;
    asm("{ .reg .u64 t; cvta.to.shared.u64 t, %1; cvt.u32.u64 %0, t; }" : "=r"(a) : "l"(p));
    return a;
}
static __device__ __forceinline__ float fast_exp2(float x) {
    float y; asm("ex2.approx.ftz.f32 %0, %1;" : "=f"(y) : "f"(x)); return y;
}
static __device__ __forceinline__ uint32_t pack_h2(float lo, float hi) {
    uint32_t u;
    asm("cvt.rn.f16x2.f32 %0, %1, %2;" : "=r"(u) : "f"(hi), "f"(lo));  // d.lo = %2
    return u;
}
static __device__ __forceinline__ uint32_t sw128(uint32_t off) {
    return off ^ ((off >> 3) & 0x70);
}
static __device__ __forceinline__ void ldsm_x4(uint32_t addr, uint32_t& r0, uint32_t& r1,
                                               uint32_t& r2, uint32_t& r3) {
    asm volatile("ldmatrix.sync.aligned.m8n8.x4.shared.b16 {%0,%1,%2,%3}, [%4];"
                 : "=r"(r0), "=r"(r1), "=r"(r2), "=r"(r3) : "r"(addr));
}
static __device__ __forceinline__ void mma16816(float* c, uint32_t a0, uint32_t a1,
                                                uint32_t a2, uint32_t a3,
                                                uint32_t b0, uint32_t b1) {
    asm volatile(
        "mma.sync.aligned.m16n8k16.row.col.f32.f16.f16.f32 "
        "{%0,%1,%2,%3}, {%4,%5,%6,%7}, {%8,%9}, {%0,%1,%2,%3};"
        : "+f"(c[0]), "+f"(c[1]), "+f"(c[2]), "+f"(c[3])
        : "r"(a0), "r"(a1), "r"(a2), "r"(a3), "r"(b0), "r"(b1));
}

// dynamic smem layout: A[2][16KB] | B[2][16KB] | bx[128] | by[128] | vc[128]
#define OFF_A    0
#define OFF_B    32768
#define OFF_BX   65536
#define OFF_BY   66048
#define OFF_VC   66560
#define SMEM_SZ  67072

// CTA = (kchunk of 128 points, channel c, batch n).
// partial[128h x 128w] = sum_p ey[h,p] * (ex[w,p] * v[p,c]) -> g_scratch (plain STG)
__global__ void __launch_bounds__(TPB)
splat2d_hmma_kernel(const float* __restrict__ coords,   // [N,P,2]
                    const float* __restrict__ values,   // [N,P,3]
                    const float* __restrict__ sigma,    // [N,1]
                    int P) {
    extern __shared__ __align__(1024) char smem[];
    float* bx = (float*)(smem + OFF_BX);
    float* by = (float*)(smem + OFF_BY);
    float* vc = (float*)(smem + OFF_VC);

    const int tid = threadIdx.x;
    const int kp  = blockIdx.x;
    const int c   = blockIdx.y;
    const int n   = blockIdx.z;
    const int p0  = kp * PCH;

    const float sg = sigma[n];
    const float a_ = sqrtf(0.72134752044448169f) / sg;   // sqrt(log2(e)/2)/sigma

    const float2* cb2 = (const float2*)coords + (size_t)n * P;
    const float*  vb  = values + (size_t)n * P * 3;

    if (tid < PCH) {
        const float2 cd = cb2[p0 + tid];
        bx[tid] = a_ * cd.x;
        by[tid] = a_ * cd.y;
        vc[tid] = vb[(p0 + tid) * 3 + c];
    }
    __syncthreads();

    const uint32_t Abase = s2u(smem + OFF_A);
    const uint32_t Bbase = s2u(smem + OFF_B);

    // ---- A tiles: ey[h][p], 2 sub-tiles of 128h x 64p fp16, SW128 128B rows ----
    for (int task = tid; task < 2048; task += TPB) {
        const int h   = task >> 4;
        const int pg  = task & 15;          // point group of 8 (0..15)
        const int ts  = pg >> 3;            // sub-tile 0/1
        const int pgl = pg & 7;
        const float ah = a_ * (float)h;
        float e[8];
        #pragma unroll
        for (int i = 0; i < 8; ++i) {
            const float d = ah - by[pg * 8 + i];
            e[i] = fast_exp2(-d * d);
        }
        const uint32_t q0 = pack_h2(e[0], e[1]);
        const uint32_t q1 = pack_h2(e[2], e[3]);
        const uint32_t q2 = pack_h2(e[4], e[5]);
        const uint32_t q3 = pack_h2(e[6], e[7]);
        asm volatile("st.shared.v4.b32 [%0], {%1,%2,%3,%4};"
                     :: "r"(Abase + ts * 16384 + sw128((uint32_t)(h * 128 + pgl * 16))),
                        "r"(q0), "r"(q1), "r"(q2), "r"(q3));
    }
    // ---- B tiles: (ex * vc)[w][p], same layout ----
    for (int task = tid; task < 2048; task += TPB) {
        const int w   = task >> 4;
        const int pg  = task & 15;
        const int ts  = pg >> 3;
        const int pgl = pg & 7;
        const float aw = a_ * (float)w;
        float m[8];
        #pragma unroll
        for (int i = 0; i < 8; ++i) {
            const float d = aw - bx[pg * 8 + i];
            m[i] = fast_exp2(-d * d) * vc[pg * 8 + i];
        }
        const uint32_t q0 = pack_h2(m[0], m[1]);
        const uint32_t q1 = pack_h2(m[2], m[3]);
        const uint32_t q2 = pack_h2(m[4], m[5]);
        const uint32_t q3 = pack_h2(m[6], m[7]);
        asm volatile("st.shared.v4.b32 [%0], {%1,%2,%3,%4};"
                     :: "r"(Bbase + ts * 16384 + sw128((uint32_t)(w * 128 + pgl * 16))),
                        "r"(q0), "r"(q1), "r"(q2), "r"(q3));
    }
    __syncthreads();

    // ---- consumer: 8 warps, warp tile 32h x 64w, 2 sub-tiles x 4 K-steps ----
    const int wid  = tid >> 5;
    const int lane = tid & 31;
    const int h0   = (wid & 3) * 32;
    const int w0   = (wid >> 2) * 64;

    float acc[2][8][4];
    #pragma unroll
    for (int mb = 0; mb < 2; ++mb)
        #pragma unroll
        for (int nb = 0; nb < 8; ++nb)
            #pragma unroll
            for (int j = 0; j < 4; ++j) acc[mb][nb][j] = 0.f;

    const int a_row = lane & 15;
    const int a_kb  = (lane >> 4) << 4;
    const int b_row = (((lane >> 4) & 1) << 3) + (lane & 7);
    const int b_kb  = ((lane >> 3) & 1) << 4;

    #pragma unroll
    for (int ts = 0; ts < 2; ++ts) {
        const uint32_t Asub = Abase + ts * 16384;
        const uint32_t Bsub = Bbase + ts * 16384;
        #pragma unroll
        for (int ks = 0; ks < 4; ++ks) {
            const uint32_t kbyte = ks * 32;   // 16 f16 per K-step

            uint32_t a[2][4];
            #pragma unroll
            for (int mb = 0; mb < 2; ++mb) {
                const uint32_t row = (uint32_t)(h0 + mb * 16 + a_row);
                ldsm_x4(Asub + sw128(row * 128 + kbyte + a_kb),
                        a[mb][0], a[mb][1], a[mb][2], a[mb][3]);
            }
            uint32_t b[4][4];
            #pragma unroll
            for (int nb16 = 0; nb16 < 4; ++nb16) {
                const uint32_t row = (uint32_t)(w0 + nb16 * 16 + b_row);
                ldsm_x4(Bsub + sw128(row * 128 + kbyte + b_kb),
                        b[nb16][0], b[nb16][1], b[nb16][2], b[nb16][3]);
            }
            #pragma unroll
            for (int mb = 0; mb < 2; ++mb)
                #pragma unroll
                for (int nb = 0; nb < 8; ++nb)
                    mma16816(acc[mb][nb],
                             a[mb][0], a[mb][1], a[mb][2], a[mb][3],
                             b[nb >> 1][(nb & 1) ? 2 : 0], b[nb >> 1][(nb & 1) ? 3 : 1]);
        }
    }

    // ---- epilogue: vectorized plain stores of the partial tile ----
    const int r  = lane >> 2;
    const int c2 = (lane & 3) * 2;
    float* sc = g_scratch + (size_t)kp * (12 * 16384) + (((size_t)n * 3 + c) << 14);
    #pragma unroll
    for (int mb = 0; mb < 2; ++mb) {
        #pragma unroll
        for (int nb = 0; nb < 8; ++nb) {
            const int hh = h0 + mb * 16 + r;
            const int ww = w0 + nb * 8 + c2;
            float* p = sc + hh * 128 + ww;
            *reinterpret_cast<float2*>(p) =
                make_float2(acc[mb][nb][0], acc[mb][nb][1]);
            *reinterpret_cast<float2*>(p + 8 * 128) =
                make_float2(acc[mb][nb][2], acc[mb][nb][3]);
        }
    }
}

// out4[g] = sum_k scratch4[k*49152 + g]; all loads batched for MLP.
__global__ void __launch_bounds__(TPB)
splat2d_reduce_kernel(float4* __restrict__ out, int kch) {
    const int g = blockIdx.x * TPB + threadIdx.x;
    const float4* s = reinterpret_cast<const float4*>(g_scratch);

    float4 b[KCH_MAX];
    #pragma unroll
    for (int k = 0; k < KCH_MAX; ++k)
        b[k] = (k < kch) ? s[(size_t)k * 49152 + g]
                         : make_float4(0.f, 0.f, 0.f, 0.f);

    float4 a = b[0];
    #pragma unroll
    for (int k = 1; k < KCH_MAX; ++k) {
        a.x += b[k].x; a.y += b[k].y; a.z += b[k].z; a.w += b[k].w;
    }
    out[g] = a;
}

extern "C" void kernel_launch(void* const* d_in, const int* in_sizes, int n_in,
                              void* d_out, int out_size) {
    const float* coords = (const float*)d_in[0];   // [N,P,2]
    const float* values = (const float*)d_in[1];   // [N,P,C]
    const float* sigma  = (const float*)d_in[2];   // [N,1]

    const int N = in_sizes[2];
    const int P = in_sizes[0] / (2 * N);           // 1024
    const int kch = P / PCH;                       // 8

    cudaFuncSetAttribute(splat2d_hmma_kernel,
                         cudaFuncAttributeMaxDynamicSharedMemorySize, SMEM_SZ);

    dim3 grid(kch, 3, N);                          // 8 x 3 x 4 = 96 CTAs
    splat2d_hmma_kernel<<<grid, TPB, SMEM_SZ>>>(coords, values, sigma, P);

    const int n_f4 = out_size / 4;                 // 49152
    splat2d_reduce_kernel<<<n_f4 / TPB, TPB>>>((float4*)d_out, kch);
}

// round 9
// speedup vs baseline: 1.3449x; 1.1826x over previous
#include <cuda_runtime.h>
#include <cuda_fp16.h>
#include <cstdint>
#include <math.h>

#define TPB 256
#define PCH 128                 // points per kp chunk (2 sub-tiles of 64)
#define KCH_MAX 8

// scratch partials: [kchunk][n*3+c][128*128] floats = 8*12*16384*4B = 6.3MB
__device__ float g_scratch[KCH_MAX * 12 * 16384];

static __device__ __forceinline__ uint32_t s2u(const void* p) {
    uint32_t a;
    asm("{ .reg .u64 t; cvta.to.shared.u64 t, %1; cvt.u32.u64 %0, t; }" : "=r"(a) : "l"(p));
    return a;
}
static __device__ __forceinline__ float fast_exp2(float x) {
    float y; asm("ex2.approx.ftz.f32 %0, %1;" : "=f"(y) : "f"(x)); return y;
}
static __device__ __forceinline__ uint32_t pack_h2(float lo, float hi) {
    uint32_t u;
    asm("cvt.rn.f16x2.f32 %0, %1, %2;" : "=r"(u) : "f"(hi), "f"(lo));  // d.lo = %2
    return u;
}
static __device__ __forceinline__ uint32_t sw128(uint32_t off) {
    return off ^ ((off >> 3) & 0x70);
}
static __device__ __forceinline__ void ldsm_x4(uint32_t addr, uint32_t& r0, uint32_t& r1,
                                               uint32_t& r2, uint32_t& r3) {
    asm volatile("ldmatrix.sync.aligned.m8n8.x4.shared.b16 {%0,%1,%2,%3}, [%4];"
                 : "=r"(r0), "=r"(r1), "=r"(r2), "=r"(r3) : "r"(addr));
}
static __device__ __forceinline__ void mma16816(float* c, uint32_t a0, uint32_t a1,
                                                uint32_t a2, uint32_t a3,
                                                uint32_t b0, uint32_t b1) {
    asm volatile(
        "mma.sync.aligned.m16n8k16.row.col.f32.f16.f16.f32 "
        "{%0,%1,%2,%3}, {%4,%5,%6,%7}, {%8,%9}, {%0,%1,%2,%3};"
        : "+f"(c[0]), "+f"(c[1]), "+f"(c[2]), "+f"(c[3])
        : "r"(a0), "r"(a1), "r"(a2), "r"(a3), "r"(b0), "r"(b1));
}

// dynamic smem: A[2][8KB] (64h x 64p each) | B[2][16KB] (128w x 64p) | bx,by,vc[128]
#define OFF_A    0
#define OFF_B    16384
#define OFF_BX   49152
#define OFF_BY   49664
#define OFF_VC   50176
#define SMEM_SZ  50688

// CTA = (kp chunk of 128 points, h-half, channel c, batch n).
// partial[64h x 128w] = sum_p ey[h,p] * (ex[w,p] * v[p,c]) -> g_scratch rows (plain STG)
__global__ void __launch_bounds__(TPB, 2)
splat2d_hmma_kernel(const float* __restrict__ coords,   // [N,P,2]
                    const float* __restrict__ values,   // [N,P,3]
                    const float* __restrict__ sigma,    // [N,1]
                    int P) {
    extern __shared__ __align__(1024) char smem[];
    float* bx = (float*)(smem + OFF_BX);
    float* by = (float*)(smem + OFF_BY);
    float* vc = (float*)(smem + OFF_VC);

    const int tid = threadIdx.x;
    const int kp  = blockIdx.x >> 1;
    const int hh  = blockIdx.x & 1;         // h-half: rows [hh*64, hh*64+64)
    const int c   = blockIdx.y;
    const int n   = blockIdx.z;
    const int p0  = kp * PCH;
    const int hbase = hh * 64;

    const float sg = sigma[n];
    const float a_ = sqrtf(0.72134752044448169f) / sg;   // sqrt(log2(e)/2)/sigma

    const float2* cb2 = (const float2*)coords + (size_t)n * P;
    const float*  vb  = values + (size_t)n * P * 3;

    if (tid < PCH) {
        const float2 cd = cb2[p0 + tid];
        bx[tid] = a_ * cd.x;
        by[tid] = a_ * cd.y;
        vc[tid] = vb[(p0 + tid) * 3 + c];
    }
    __syncthreads();

    const uint32_t Abase = s2u(smem + OFF_A);
    const uint32_t Bbase = s2u(smem + OFF_B);

    // ---- A tiles: ey[h][p], 64h x 128p as 2 sub-tiles of 64h x 64p, SW128 ----
    // task -> h = task & 63 (lane-consecutive), pg = task >> 6 (warp-uniform broadcast)
    for (int task = tid; task < 1024; task += TPB) {
        const int h   = task & 63;
        const int pg  = task >> 6;          // 0..15
        const int ts  = pg >> 3;
        const int pgl = pg & 7;
        const float ah = a_ * (float)(hbase + h);
        float e[8];
        #pragma unroll
        for (int i = 0; i < 8; ++i) {
            const float d = ah - by[pg * 8 + i];   // broadcast
            e[i] = fast_exp2(-d * d);
        }
        const uint32_t q0 = pack_h2(e[0], e[1]);
        const uint32_t q1 = pack_h2(e[2], e[3]);
        const uint32_t q2 = pack_h2(e[4], e[5]);
        const uint32_t q3 = pack_h2(e[6], e[7]);
        asm volatile("st.shared.v4.b32 [%0], {%1,%2,%3,%4};"
                     :: "r"(Abase + ts * 8192 + sw128((uint32_t)(h * 128 + pgl * 16))),
                        "r"(q0), "r"(q1), "r"(q2), "r"(q3));
    }
    // ---- B tiles: (ex * vc)[w][p], 128w x 128p as 2 sub-tiles of 128w x 64p ----
    for (int task = tid; task < 2048; task += TPB) {
        const int w   = task & 127;
        const int pg  = task >> 7;          // 0..15, warp-uniform
        const int ts  = pg >> 3;
        const int pgl = pg & 7;
        const float aw = a_ * (float)w;
        float m[8];
        #pragma unroll
        for (int i = 0; i < 8; ++i) {
            const float d = aw - bx[pg * 8 + i];   // broadcast
            m[i] = fast_exp2(-d * d) * vc[pg * 8 + i];
        }
        const uint32_t q0 = pack_h2(m[0], m[1]);
        const uint32_t q1 = pack_h2(m[2], m[3]);
        const uint32_t q2 = pack_h2(m[4], m[5]);
        const uint32_t q3 = pack_h2(m[6], m[7]);
        asm volatile("st.shared.v4.b32 [%0], {%1,%2,%3,%4};"
                     :: "r"(Bbase + ts * 16384 + sw128((uint32_t)(w * 128 + pgl * 16))),
                        "r"(q0), "r"(q1), "r"(q2), "r"(q3));
    }
    __syncthreads();

    // ---- consumer: 8 warps, warp tile 16h x 64w, 2 sub-tiles x 4 K-steps ----
    const int wid  = tid >> 5;
    const int lane = tid & 31;
    const int h0   = (wid & 3) * 16;
    const int w0   = (wid >> 2) * 64;

    float acc[8][4];
    #pragma unroll
    for (int nb = 0; nb < 8; ++nb)
        #pragma unroll
        for (int j = 0; j < 4; ++j) acc[nb][j] = 0.f;

    const int a_row = lane & 15;
    const int a_kb  = (lane >> 4) << 4;
    const int b_row = (((lane >> 4) & 1) << 3) + (lane & 7);
    const int b_kb  = ((lane >> 3) & 1) << 4;

    #pragma unroll
    for (int ts = 0; ts < 2; ++ts) {
        const uint32_t Asub = Abase + ts * 8192;
        const uint32_t Bsub = Bbase + ts * 16384;
        #pragma unroll
        for (int ks = 0; ks < 4; ++ks) {
            const uint32_t kbyte = ks * 32;   // 16 f16 per K-step

            uint32_t a0, a1, a2, a3;
            ldsm_x4(Asub + sw128((uint32_t)((h0 + a_row) * 128) + kbyte + a_kb),
                    a0, a1, a2, a3);
            uint32_t b[4][4];
            #pragma unroll
            for (int nb16 = 0; nb16 < 4; ++nb16) {
                const uint32_t row = (uint32_t)(w0 + nb16 * 16 + b_row);
                ldsm_x4(Bsub + sw128(row * 128 + kbyte + b_kb),
                        b[nb16][0], b[nb16][1], b[nb16][2], b[nb16][3]);
            }
            #pragma unroll
            for (int nb = 0; nb < 8; ++nb)
                mma16816(acc[nb], a0, a1, a2, a3,
                         b[nb >> 1][(nb & 1) ? 2 : 0], b[nb >> 1][(nb & 1) ? 3 : 1]);
        }
    }

    // ---- epilogue: vectorized plain stores into this CTA's scratch rows ----
    const int r  = lane >> 2;
    const int c2 = (lane & 3) * 2;
    float* sc = g_scratch + (size_t)kp * (12 * 16384) + (((size_t)n * 3 + c) << 14);
    #pragma unroll
    for (int nb = 0; nb < 8; ++nb) {
        const int hhg = hbase + h0 + r;
        const int ww  = w0 + nb * 8 + c2;
        float* p = sc + hhg * 128 + ww;
        *reinterpret_cast<float2*>(p)           = make_float2(acc[nb][0], acc[nb][1]);
        *reinterpret_cast<float2*>(p + 8 * 128) = make_float2(acc[nb][2], acc[nb][3]);
    }
}

// out2[g] = sum_k scratch2[k*98304 + g]; batched loads, float2 granularity for 2x warps.
__global__ void __launch_bounds__(TPB)
splat2d_reduce_kernel(float2* __restrict__ out, int kch) {
    const int g = blockIdx.x * TPB + threadIdx.x;
    const float2* s = reinterpret_cast<const float2*>(g_scratch);

    float2 b[KCH_MAX];
    #pragma unroll
    for (int k = 0; k < KCH_MAX; ++k)
        b[k] = (k < kch) ? s[(size_t)k * 98304 + g] : make_float2(0.f, 0.f);

    float2 a = b[0];
    #pragma unroll
    for (int k = 1; k < KCH_MAX; ++k) { a.x += b[k].x; a.y += b[k].y; }
    out[g] = a;
}

extern "C" void kernel_launch(void* const* d_in, const int* in_sizes, int n_in,
                              void* d_out, int out_size) {
    const float* coords = (const float*)d_in[0];   // [N,P,2]
    const float* values = (const float*)d_in[1];   // [N,P,C]
    const float* sigma  = (const float*)d_in[2];   // [N,1]

    const int N = in_sizes[2];
    const int P = in_sizes[0] / (2 * N);           // 1024
    const int kch = P / PCH;                       // 8

    cudaFuncSetAttribute(splat2d_hmma_kernel,
                         cudaFuncAttributeMaxDynamicSharedMemorySize, SMEM_SZ);

    dim3 grid(kch * 2, 3, N);                      // 16 x 3 x 4 = 192 CTAs
    splat2d_hmma_kernel<<<grid, TPB, SMEM_SZ>>>(coords, values, sigma, P);

    const int n_f2 = out_size / 2;                 // 98304
    splat2d_reduce_kernel<<<n_f2 / TPB, TPB>>>((float2*)d_out, kch);
}